// round 11
// baseline (speedup 1.0000x reference)
#include <cuda_runtime.h>
#include <cuda_fp16.h>
#include <math.h>
#include <stdint.h>

#define NNODE 50000
#define NEDGE 800000
#define EPAD  (NEDGE + NNODE)
#define FDIM  256
#define NHEAD 4
#define OUTD  64
#define NBLK  ((NNODE + 1023) / 1024)   // 49 scan blocks

// ---------------- scratch ---------------------------------------------------
__device__ __align__(128) __half g_t[NNODE * FDIM];       // GEMM out, fp16 msgs
__device__ __align__(16) uint16_t g_h1h[NNODE * FDIM];    // layer-1 h, bf16 hi
__device__ __align__(16) uint16_t g_h1l[NNODE * FDIM];    // layer-1 h, bf16 lo
__device__ __align__(16) uint16_t g_h2h[NNODE * FDIM];
__device__ __align__(16) uint16_t g_h2l[NNODE * FDIM];
__device__ __align__(16) uint16_t g_w1h[FDIM * FDIM];     // W^T hi bf16 [N][K]
__device__ __align__(16) uint16_t g_w1l[FDIM * FDIM];
__device__ __align__(16) uint16_t g_w2h[FDIM * FDIM];
__device__ __align__(16) uint16_t g_w2l[FDIM * FDIM];
__device__ __align__(16) uint16_t g_wfh[OUTD * FDIM];
__device__ __align__(16) uint16_t g_wfl[OUTD * FDIM];
__device__ float g_als[NNODE * NHEAD];
__device__ float g_ald[NNODE * NHEAD];
__device__ int   g_deg[NNODE];
__device__ int   g_rowptr[NNODE + 1];
__device__ int   g_cursor[NNODE];
__device__ int   g_srcs[EPAD];
__device__ int   g_bsum[NBLK + 1];
__device__ int   g_boff[NBLK + 1];

__device__ __forceinline__ int clampi(int v, int lo, int hi) {
    return v < lo ? lo : (v > hi ? hi : v);
}
__device__ __forceinline__ uint32_t pack_bf16x2(float v0, float v1) {
    uint32_t d;
    asm("cvt.rn.bf16x2.f32 %0, %1, %2;" : "=r"(d) : "f"(v1), "f"(v0));
    return d;
}
__device__ __forceinline__ void mma_bf16(float* d, const uint32_t* a, const uint32_t* b) {
    asm volatile(
        "mma.sync.aligned.m16n8k16.row.col.f32.bf16.bf16.f32 "
        "{%0,%1,%2,%3}, {%4,%5,%6,%7}, {%8,%9}, {%0,%1,%2,%3};"
        : "+f"(d[0]), "+f"(d[1]), "+f"(d[2]), "+f"(d[3])
        : "r"(a[0]), "r"(a[1]), "r"(a[2]), "r"(a[3]), "r"(b[0]), "r"(b[1]));
}
#define LDSM_X4(r, addr)                                                     \
    asm volatile("ldmatrix.sync.aligned.m8n8.x4.shared.b16 {%0,%1,%2,%3}, [%4];" \
        : "=r"((r)[0]), "=r"((r)[1]), "=r"((r)[2]), "=r"((r)[3]) : "r"(addr))
#define CP_A16(dst, src, sz)                                                 \
    asm volatile("cp.async.cg.shared.global [%0], [%1], 16, %2;"             \
        :: "r"(dst), "l"(src), "r"(sz))
#define CP_COMMIT() asm volatile("cp.async.commit_group;" ::: "memory")
#define CP_WAIT0()  asm volatile("cp.async.wait_group 0;" ::: "memory")

// ---------------- CSR construction ------------------------------------------
__global__ void k_count_deg(const int* __restrict__ ei, int* deg) {
    int e = blockIdx.x * blockDim.x + threadIdx.x;
    if (e < NEDGE) atomicAdd(&deg[clampi(ei[NEDGE + e], 0, NNODE - 1)], 1);
}
__global__ void k_scan1(const int* __restrict__ deg, int* rowptr, int* bsum) {
    int b = blockIdx.x, tid = threadIdx.x;
    int i = b * 1024 + tid;
    int v = (i < NNODE) ? (deg[i] + 1) : 0;   // +1 self loop
    int lane = tid & 31, w = tid >> 5;
    int x = v;
#pragma unroll
    for (int off = 1; off < 32; off <<= 1) {
        int y = __shfl_up_sync(0xffffffffu, x, off);
        if (lane >= off) x += y;
    }
    __shared__ int ws[32];
    if (lane == 31) ws[w] = x;
    __syncthreads();
    if (w == 0) {
        int s = ws[lane];
#pragma unroll
        for (int off = 1; off < 32; off <<= 1) {
            int y = __shfl_up_sync(0xffffffffu, s, off);
            if (lane >= off) s += y;
        }
        ws[lane] = s;
    }
    __syncthreads();
    int wo = (w > 0) ? ws[w - 1] : 0;
    int incl = x + wo;
    if (i < NNODE) rowptr[i] = incl - v;
    if (tid == 1023) bsum[b] = incl;
}
__global__ void k_scan2(const int* __restrict__ bsum, int* boff, int* rowptr) {
    if (threadIdx.x == 0) {
        int s = 0;
        for (int b = 0; b < NBLK; b++) { boff[b] = s; s += bsum[b]; }
        rowptr[NNODE] = s;
    }
}
__global__ void k_scan3(int* rowptr, int* cursor, const int* __restrict__ boff) {
    int i = blockIdx.x * blockDim.x + threadIdx.x;
    if (i < NNODE) {
        int r = rowptr[i] + boff[i >> 10];
        rowptr[i] = r;
        cursor[i] = r;
    }
}
__global__ void k_scatter(const int* __restrict__ ei, int* cursor, int* srcs) {
    int e = blockIdx.x * blockDim.x + threadIdx.x;
    if (e < NEDGE) {
        int s = clampi(ei[e], 0, NNODE - 1);
        int d = clampi(ei[NEDGE + e], 0, NNODE - 1);
        int pos = atomicAdd(&cursor[d], 1);
        if (pos >= 0 && pos < EPAD) srcs[pos] = s;
    } else if (e < EPAD) {
        int i = e - NEDGE;
        int pos = atomicAdd(&cursor[i], 1);
        if (pos >= 0 && pos < EPAD) srcs[pos] = i;
    }
}

// ---------------- weight split/transpose: W[K][N] -> hi/lo bf16 [N][K] ------
__global__ void k_split_w(const float* __restrict__ W, uint16_t* __restrict__ WH,
                          uint16_t* __restrict__ WL, int K, int N) {
    int i = blockIdx.x * blockDim.x + threadIdx.x;
    if (i < K * N) {
        int k = i / N, n = i % N;
        float v = W[i];
        uint32_t hw = pack_bf16x2(v, 0.f);
        float hf = __uint_as_float(hw << 16);
        uint32_t lw = pack_bf16x2(v - hf, 0.f);
        WH[n * K + k] = (uint16_t)(hw & 0xffffu);
        WL[n * K + k] = (uint16_t)(lw & 0xffffu);
    }
}

// ---------------- bf16-split tensor-core GEMM + fused logits ----------------
// Double-buffered smem (1 sync per K-tile). PRESPLIT path: pure cp.async.
// GEMM1 path: A fp32 staged via regs (split in flight), B via cp.async.
template<int BN, int NOUT, bool PRESPLIT, bool HALF_C>
__global__ void __launch_bounds__(256, 2)
k_gemm_mma(const float* __restrict__ A,
           const uint16_t* __restrict__ AH, const uint16_t* __restrict__ AL,
           const uint16_t* __restrict__ BH, const uint16_t* __restrict__ BL,
           const float* __restrict__ bias, void* __restrict__ C, int M,
           const float* __restrict__ a_src, const float* __restrict__ a_dst,
           float* __restrict__ als_out, float* __restrict__ ald_out) {
    constexpr int RS = 40;                 // smem row stride (halves)
    constexpr int WN = BN / 2;
    constexpr int NT = WN / 8;
    constexpr int NP = NT / 2;
    constexpr int ABYTES = 128 * RS * 2;   // 10240
    constexpr int BBYTES = BN * RS * 2;
    constexpr int AOFF_H = 0, AOFF_L = ABYTES;
    constexpr int BOFF_H = 2 * ABYTES, BOFF_L = 2 * ABYTES + BBYTES;
    constexpr int STAGE = 2 * ABYTES + 2 * BBYTES;
    constexpr int B_CH = BN / 64;          // 16B chunks per thread per B array

    extern __shared__ __align__(16) char smem[];
    const uint32_t sb = (uint32_t)__cvta_generic_to_shared(smem);

    const int tid  = threadIdx.x;
    const int wid  = tid >> 5, lane = tid & 31;
    const int wm   = wid & 3, wn = wid >> 2;
    const int g    = lane >> 2, tq = lane & 3;
    const int brow = blockIdx.x * 128;
    const int bcol = blockIdx.y * BN;

    float acc[2][NT][4];
#pragma unroll
    for (int mt = 0; mt < 2; mt++)
#pragma unroll
        for (int nt = 0; nt < NT; nt++)
#pragma unroll
            for (int r = 0; r < 4; r++) acc[mt][nt][r] = 0.f;

    // per-lane ldmatrix byte offsets (within each array)
    const int lane8 = lane & 7, lh = (lane >> 3) & 1, lq = lane >> 4;
    uint32_t aOff[2], bOff[NP];
#pragma unroll
    for (int mt = 0; mt < 2; mt++) {
        int ar = wm * 32 + mt * 16 + lane8 + lh * 8;
        aOff[mt] = (uint32_t)(ar * RS + lq * 8) * 2;
    }
#pragma unroll
    for (int p = 0; p < NP; p++) {
        int br = wn * WN + p * 16 + lane8 + lq * 8;
        bOff[p] = (uint32_t)(br * RS + lh * 8) * 2;
    }

    // cp.async issue of B (always) into given stage
    auto cpB = [&](int k0, int stage) {
        uint32_t sbase = sb + stage * STAGE;
#pragma unroll
        for (int u = 0; u < B_CH; u++) {
            int q = tid + u * 256;
            int row = q >> 2, c8 = q & 3;
            size_t gi = (size_t)(bcol + row) * 256 + k0 + c8 * 8;
            uint32_t d = sbase + (uint32_t)(row * (RS * 2) + c8 * 16);
            CP_A16(d + BOFF_H, BH + gi, 16);
            CP_A16(d + BOFF_L, BL + gi, 16);
        }
    };
    // cp.async issue of A (PRESPLIT only)
    auto cpA = [&](int k0, int stage) {
        uint32_t sbase = sb + stage * STAGE;
#pragma unroll
        for (int u = 0; u < 2; u++) {
            int q = tid + u * 256;
            int row = q >> 2, c8 = q & 3;
            int gr = brow + row;
            int sz = (gr < M) ? 16 : 0;
            int grc = (gr < M) ? gr : 0;
            size_t gi = (size_t)grc * 256 + k0 + c8 * 8;
            uint32_t d = sbase + (uint32_t)(row * (RS * 2) + c8 * 16);
            CP_A16(d + AOFF_H, AH + gi, sz);
            CP_A16(d + AOFF_L, AL + gi, sz);
        }
    };

    // register staging for fp32 A (GEMM1 path)
    float4 aS[4];
    auto loadA = [&](int k0) {
#pragma unroll
        for (int u = 0; u < 4; u++) {
            int q = tid + u * 256;
            int row = q >> 3, f4 = q & 7;
            int gr = brow + row;
            aS[u] = make_float4(0.f, 0.f, 0.f, 0.f);
            if (gr < M) aS[u] = *reinterpret_cast<const float4*>(&A[(size_t)gr * 256 + k0 + f4 * 4]);
        }
    };
    auto storeA = [&](int stage) {
        uint16_t* pAh = reinterpret_cast<uint16_t*>(smem + stage * STAGE + AOFF_H);
        uint16_t* pAl = reinterpret_cast<uint16_t*>(smem + stage * STAGE + AOFF_L);
#pragma unroll
        for (int u = 0; u < 4; u++) {
            int q = tid + u * 256;
            int row = q >> 3, f4 = q & 7;
            int idx = row * RS + f4 * 4;
            float v[4] = {aS[u].x, aS[u].y, aS[u].z, aS[u].w};
#pragma unroll
            for (int h2i = 0; h2i < 2; h2i++) {
                uint32_t hw = pack_bf16x2(v[h2i * 2], v[h2i * 2 + 1]);
                float f0 = __uint_as_float(hw << 16);
                float f1 = __uint_as_float(hw & 0xffff0000u);
                uint32_t lw = pack_bf16x2(v[h2i * 2] - f0, v[h2i * 2 + 1] - f1);
                *reinterpret_cast<uint32_t*>(pAh + idx + h2i * 2) = hw;
                *reinterpret_cast<uint32_t*>(pAl + idx + h2i * 2) = lw;
            }
        }
    };

    auto compute = [&](int stage) {
        uint32_t sbase = sb + stage * STAGE;
#pragma unroll
        for (int ks = 0; ks < 2; ks++) {
            const uint32_t kb = ks * 32;
            uint32_t ah[2][4], al[2][4];
            LDSM_X4(ah[0], sbase + AOFF_H + aOff[0] + kb);
            LDSM_X4(ah[1], sbase + AOFF_H + aOff[1] + kb);
            LDSM_X4(al[0], sbase + AOFF_L + aOff[0] + kb);
            LDSM_X4(al[1], sbase + AOFF_L + aOff[1] + kb);
#pragma unroll
            for (int p = 0; p < NP; p++) {
                uint32_t bh[4], bl[4];
                LDSM_X4(bh, sbase + BOFF_H + bOff[p] + kb);
                LDSM_X4(bl, sbase + BOFF_L + bOff[p] + kb);
#pragma unroll
                for (int mt = 0; mt < 2; mt++) {
                    mma_bf16(acc[mt][2 * p],     ah[mt], bh);
                    mma_bf16(acc[mt][2 * p],     ah[mt], bl);
                    mma_bf16(acc[mt][2 * p],     al[mt], bh);
                    mma_bf16(acc[mt][2 * p + 1], ah[mt], bh + 2);
                    mma_bf16(acc[mt][2 * p + 1], ah[mt], bl + 2);
                    mma_bf16(acc[mt][2 * p + 1], al[mt], bh + 2);
                }
            }
        }
    };

    // ---- pipelined mainloop (8 K-tiles of 32), 2 smem stages, 1 sync/tile --
    if (PRESPLIT) {
        cpA(0, 0); cpB(0, 0); CP_COMMIT();
        CP_WAIT0(); __syncthreads();
        int buf = 0;
        for (int t = 0; t < 8; t++) {
            if (t < 7) { cpA((t + 1) * 32, buf ^ 1); cpB((t + 1) * 32, buf ^ 1); CP_COMMIT(); }
            compute(buf);
            if (t < 7) { CP_WAIT0(); __syncthreads(); buf ^= 1; }
        }
    } else {
        cpB(0, 0); CP_COMMIT();
        loadA(0); storeA(0);
        CP_WAIT0(); __syncthreads();
        int buf = 0;
        for (int t = 0; t < 8; t++) {
            if (t < 7) { cpB((t + 1) * 32, buf ^ 1); CP_COMMIT(); loadA((t + 1) * 32); }
            compute(buf);
            if (t < 7) { storeA(buf ^ 1); CP_WAIT0(); __syncthreads(); buf ^= 1; }
        }
    }

    // epilogue
#pragma unroll
    for (int mt = 0; mt < 2; mt++) {
        int r0 = brow + wm * 32 + mt * 16 + g;
        int r1 = r0 + 8;
#pragma unroll
        for (int nt = 0; nt < NT; nt++) {
            int col = bcol + wn * WN + nt * 8 + tq * 2;
            if (HALF_C) {
                __half2* Ch = reinterpret_cast<__half2*>(C);
                if (r0 < M)
                    Ch[(size_t)r0 * (NOUT / 2) + col / 2] =
                        __floats2half2_rn(acc[mt][nt][0], acc[mt][nt][1]);
                if (r1 < M)
                    Ch[(size_t)r1 * (NOUT / 2) + col / 2] =
                        __floats2half2_rn(acc[mt][nt][2], acc[mt][nt][3]);
            } else {
                float* Cf = reinterpret_cast<float*>(C);
                float b0 = 0.f, b1 = 0.f;
                if (bias) { b0 = bias[col]; b1 = bias[col + 1]; }
                if (r0 < M)
                    *reinterpret_cast<float2*>(&Cf[(size_t)r0 * NOUT + col]) =
                        make_float2(acc[mt][nt][0] + b0, acc[mt][nt][1] + b1);
                if (r1 < M)
                    *reinterpret_cast<float2*>(&Cf[(size_t)r1 * NOUT + col]) =
                        make_float2(acc[mt][nt][2] + b0, acc[mt][nt][3] + b1);
            }
        }
    }

    // fused attention logits (BN==128): head = blockIdx.y*2 + wn (fp32 acc)
    if (als_out) {
        int head = blockIdx.y * 2 + wn;
#pragma unroll
        for (int mt = 0; mt < 2; mt++) {
#pragma unroll
            for (int half = 0; half < 2; half++) {
                float ps = 0.f, pd = 0.f;
#pragma unroll
                for (int nt = 0; nt < NT; nt++) {
                    int col = bcol + wn * WN + nt * 8 + tq * 2;
                    float a0 = acc[mt][nt][half * 2 + 0];
                    float a1 = acc[mt][nt][half * 2 + 1];
                    ps += a0 * a_src[col] + a1 * a_src[col + 1];
                    pd += a0 * a_dst[col] + a1 * a_dst[col + 1];
                }
                ps += __shfl_xor_sync(0xffffffffu, ps, 1);
                pd += __shfl_xor_sync(0xffffffffu, pd, 1);
                ps += __shfl_xor_sync(0xffffffffu, ps, 2);
                pd += __shfl_xor_sync(0xffffffffu, pd, 2);
                int row = brow + wm * 32 + mt * 16 + g + half * 8;
                if (tq == 0 && row < M) {
                    als_out[row * NHEAD + head] = ps;
                    ald_out[row * NHEAD + head] = pd;
                }
            }
        }
    }
}

// ---------------- warp-synchronous aggregation (fp16 messages) --------------
// 4 nodes per block; warp w owns head w. Channels as 32 half2 per head.
__global__ void __launch_bounds__(128)
k_gat_aggregate(const __half2* __restrict__ hsrc,
                const int* __restrict__ rowptr,
                const int* __restrict__ srcs,
                const float* __restrict__ als,
                const float* __restrict__ ald,
                const float* __restrict__ bias,
                uint16_t* __restrict__ outh, uint16_t* __restrict__ outl) {
    int w = threadIdx.x >> 5;    // head == warp
    int lane = threadIdx.x & 31;
    int c2 = w * 32 + lane;
    float b0 = bias[2 * c2], b1 = bias[2 * c2 + 1];

    int n0 = blockIdx.x * 4;
    int nend = n0 + 4 < NNODE ? n0 + 4 : NNODE;
    for (int n = n0; n < nend; n++) {
        int p0  = rowptr[n];
        int deg = rowptr[n + 1] - p0;

        float aldv = __ldg(&ald[n * NHEAD + w]);
        float accx = 0.f, accy = 0.f, dsum = 0.f;

        for (int base = 0; base < deg; base += 32) {
            int j = base + lane;
            int s = 0;
            float wt = 0.f;
            if (j < deg) {
                s = srcs[p0 + j];
                float e = als[s * NHEAD + w] + aldv;
                e = (e > 0.f) ? e : 0.2f * e;
                wt = __expf(e);
                dsum += wt;
            }
            int lim = min(32, deg - base);
#pragma unroll 4
            for (int j2 = 0; j2 < lim; j2++) {
                int   ss = __shfl_sync(0xffffffffu, s,  j2);
                float ww = __shfl_sync(0xffffffffu, wt, j2);
                float2 v = __half22float2(hsrc[(size_t)ss * 128 + c2]);
                accx += ww * v.x;
                accy += ww * v.y;
            }
        }

#pragma unroll
        for (int off = 16; off >= 1; off >>= 1)
            dsum += __shfl_xor_sync(0xffffffffu, dsum, off);

        float inv = 1.f / dsum;
        float o0 = accx * inv + b0;
        float o1 = accy * inv + b1;
        o0 = (o0 > 0.f) ? o0 : expm1f(o0);
        o1 = (o1 > 0.f) ? o1 : expm1f(o1);

        uint32_t hw = pack_bf16x2(o0, o1);
        float f0 = __uint_as_float(hw << 16);
        float f1 = __uint_as_float(hw & 0xffff0000u);
        uint32_t lw = pack_bf16x2(o0 - f0, o1 - f1);
        reinterpret_cast<uint32_t*>(outh)[(size_t)n * 128 + c2] = hw;
        reinterpret_cast<uint32_t*>(outl)[(size_t)n * 128 + c2] = lw;
    }
}

// ---------------- launch ----------------------------------------------------
extern "C" void kernel_launch(void* const* d_in, const int* in_sizes, int n_in,
                              void* d_out, int out_size) {
    const float* x     = (const float*)d_in[0];
    const int*   ei    = (const int*)d_in[1];   // int32 (JAX x64 disabled)
    const float* W1    = (const float*)d_in[3];
    const float* asrc1 = (const float*)d_in[4];
    const float* adst1 = (const float*)d_in[5];
    const float* b1    = (const float*)d_in[6];
    const float* W2    = (const float*)d_in[7];
    const float* asrc2 = (const float*)d_in[8];
    const float* adst2 = (const float*)d_in[9];
    const float* b2    = (const float*)d_in[10];
    const float* fcW   = (const float*)d_in[11];
    const float* fcb   = (const float*)d_in[12];
    float* out = (float*)d_out;

    __half* t;
    float *als, *ald;
    uint16_t *h1h, *h1l, *h2h, *h2l;
    uint16_t *w1h, *w1l, *w2h, *w2l, *wfh, *wfl;
    int *deg, *rowptr, *cursor, *srcs, *bsum, *boff;
    cudaGetSymbolAddress((void**)&t, g_t);
    cudaGetSymbolAddress((void**)&h1h, g_h1h);
    cudaGetSymbolAddress((void**)&h1l, g_h1l);
    cudaGetSymbolAddress((void**)&h2h, g_h2h);
    cudaGetSymbolAddress((void**)&h2l, g_h2l);
    cudaGetSymbolAddress((void**)&als, g_als);
    cudaGetSymbolAddress((void**)&ald, g_ald);
    cudaGetSymbolAddress((void**)&w1h, g_w1h);
    cudaGetSymbolAddress((void**)&w1l, g_w1l);
    cudaGetSymbolAddress((void**)&w2h, g_w2h);
    cudaGetSymbolAddress((void**)&w2l, g_w2l);
    cudaGetSymbolAddress((void**)&wfh, g_wfh);
    cudaGetSymbolAddress((void**)&wfl, g_wfl);
    cudaGetSymbolAddress((void**)&deg, g_deg);
    cudaGetSymbolAddress((void**)&rowptr, g_rowptr);
    cudaGetSymbolAddress((void**)&cursor, g_cursor);
    cudaGetSymbolAddress((void**)&srcs, g_srcs);
    cudaGetSymbolAddress((void**)&bsum, g_bsum);
    cudaGetSymbolAddress((void**)&boff, g_boff);

    constexpr int SMEM_BIG = 2 * (2 * 10240 + 2 * 10240);   // 81920
    constexpr int SMEM_FC  = 2 * (2 * 10240 + 2 * 5120);    // 61440

    // one-time init (first call = correctness run, outside graph capture)
    static cudaStream_t s2 = nullptr;
    static cudaEvent_t evFork = nullptr, evJoin = nullptr;
    if (s2 == nullptr) {
        cudaStreamCreateWithFlags(&s2, cudaStreamNonBlocking);
        cudaEventCreateWithFlags(&evFork, cudaEventDisableTiming);
        cudaEventCreateWithFlags(&evJoin, cudaEventDisableTiming);
        cudaFuncSetAttribute((const void*)k_gemm_mma<128, 256, false, true>,
                             cudaFuncAttributeMaxDynamicSharedMemorySize, SMEM_BIG);
        cudaFuncSetAttribute((const void*)k_gemm_mma<128, 256, true, true>,
                             cudaFuncAttributeMaxDynamicSharedMemorySize, SMEM_BIG);
        cudaFuncSetAttribute((const void*)k_gemm_mma<64, 64, true, false>,
                             cudaFuncAttributeMaxDynamicSharedMemorySize, SMEM_FC);
    }

    const int NTILE = (NNODE + 127) / 128;   // 391
    dim3 gbig(NTILE, 2);
    dim3 gfc(NTILE, 1);

    // fork side stream
    cudaEventRecord(evFork, 0);
    cudaStreamWaitEvent(s2, evFork, 0);

    // main #1 (overall #3 after 2 harness kernels)
    k_split_w<<<(FDIM * FDIM + 255) / 256, 256>>>(W1, w1h, w1l, FDIM, FDIM);
    cudaMemsetAsync(deg, 0, NNODE * sizeof(int), s2);
    k_count_deg<<<(NEDGE + 255) / 256, 256, 0, s2>>>(ei, deg);
    k_scan1<<<NBLK, 1024, 0, s2>>>(deg, rowptr, bsum);

    // overall #6: layer-1 GEMM (profiled by ncu -s 5 -c 1)
    k_gemm_mma<128, 256, false, true><<<gbig, 256, SMEM_BIG>>>(
        x, nullptr, nullptr, w1h, w1l, nullptr, t, NNODE, asrc1, adst1, als, ald);

    // rest of CSR + weight splits on side stream
    k_scan2<<<1, 32, 0, s2>>>(bsum, boff, rowptr);
    k_scan3<<<NBLK, 1024, 0, s2>>>(rowptr, cursor, boff);
    k_scatter<<<(EPAD + 255) / 256, 256, 0, s2>>>(ei, cursor, srcs);
    k_split_w<<<(FDIM * FDIM + 255) / 256, 256, 0, s2>>>(W2, w2h, w2l, FDIM, FDIM);
    k_split_w<<<(FDIM * OUTD + 255) / 256, 256, 0, s2>>>(fcW, wfh, wfl, FDIM, OUTD);
    cudaEventRecord(evJoin, s2);

    // join: aggregation needs CSR; layer-2 GEMM needs W2 split
    cudaStreamWaitEvent(0, evJoin, 0);

    const int AGG_BLK = (NNODE + 3) / 4;   // 12500

    // layer 1 aggregate -> h1 (bf16 split)
    k_gat_aggregate<<<AGG_BLK, 128>>>((const __half2*)t, rowptr, srcs, als, ald,
                                      b1, h1h, h1l);

    // layer 2
    k_gemm_mma<128, 256, true, true><<<gbig, 256, SMEM_BIG>>>(
        nullptr, h1h, h1l, w2h, w2l, nullptr, t, NNODE, asrc2, adst2, als, ald);
    k_gat_aggregate<<<AGG_BLK, 128>>>((const __half2*)t, rowptr, srcs, als, ald,
                                      b2, h2h, h2l);

    // fc head (fp32 out + bias)
    k_gemm_mma<64, 64, true, false><<<gfc, 256, SMEM_FC>>>(
        nullptr, h2h, h2l, wfh, wfl, fcb, out, NNODE,
        nullptr, nullptr, nullptr, nullptr);
}

// round 12
// speedup vs baseline: 1.1018x; 1.1018x over previous
#include <cuda_runtime.h>
#include <cuda_fp16.h>
#include <math.h>
#include <stdint.h>

#define NNODE 50000
#define NEDGE 800000
#define EPAD  (NEDGE + NNODE)
#define FDIM  256
#define NHEAD 4
#define OUTD  64
#define NBLK  ((NNODE + 1023) / 1024)   // 49 scan blocks

// ---------------- scratch ---------------------------------------------------
__device__ __align__(128) __half g_t[NNODE * FDIM];       // GEMM out, fp16 msgs
__device__ __align__(16) uint16_t g_h1h[NNODE * FDIM];    // layer-1 h, bf16 hi
__device__ __align__(16) uint16_t g_h1l[NNODE * FDIM];    // layer-1 h, bf16 lo
__device__ __align__(16) uint16_t g_h2h[NNODE * FDIM];
__device__ __align__(16) uint16_t g_h2l[NNODE * FDIM];
__device__ __align__(16) uint16_t g_w1h[FDIM * FDIM];     // W^T hi bf16 [N][K]
__device__ __align__(16) uint16_t g_w1l[FDIM * FDIM];
__device__ __align__(16) uint16_t g_w2h[FDIM * FDIM];
__device__ __align__(16) uint16_t g_w2l[FDIM * FDIM];
__device__ __align__(16) uint16_t g_wfh[OUTD * FDIM];
__device__ __align__(16) uint16_t g_wfl[OUTD * FDIM];
__device__ float g_als[NNODE * NHEAD];
__device__ float g_ald[NNODE * NHEAD];
__device__ int   g_deg[NNODE];
__device__ int   g_rowptr[NNODE + 1];
__device__ int   g_cursor[NNODE];
__device__ int   g_srcs[EPAD];
__device__ int   g_bsum[NBLK + 1];
__device__ int   g_boff[NBLK + 1];

__device__ __forceinline__ int clampi(int v, int lo, int hi) {
    return v < lo ? lo : (v > hi ? hi : v);
}
__device__ __forceinline__ uint32_t pack_bf16x2(float v0, float v1) {
    uint32_t d;
    asm("cvt.rn.bf16x2.f32 %0, %1, %2;" : "=r"(d) : "f"(v1), "f"(v0));
    return d;
}
__device__ __forceinline__ void mma_bf16(float* d, const uint32_t* a, const uint32_t* b) {
    asm volatile(
        "mma.sync.aligned.m16n8k16.row.col.f32.bf16.bf16.f32 "
        "{%0,%1,%2,%3}, {%4,%5,%6,%7}, {%8,%9}, {%0,%1,%2,%3};"
        : "+f"(d[0]), "+f"(d[1]), "+f"(d[2]), "+f"(d[3])
        : "r"(a[0]), "r"(a[1]), "r"(a[2]), "r"(a[3]), "r"(b[0]), "r"(b[1]));
}
#define LDSM_X4(r, addr)                                                     \
    asm volatile("ldmatrix.sync.aligned.m8n8.x4.shared.b16 {%0,%1,%2,%3}, [%4];" \
        : "=r"((r)[0]), "=r"((r)[1]), "=r"((r)[2]), "=r"((r)[3]) : "r"(addr))
#define CP_A16(dst, src, sz)                                                 \
    asm volatile("cp.async.cg.shared.global [%0], [%1], 16, %2;"             \
        :: "r"(dst), "l"(src), "r"(sz))
#define CP_COMMIT() asm volatile("cp.async.commit_group;" ::: "memory")
#define CP_WAIT0()  asm volatile("cp.async.wait_group 0;" ::: "memory")

// ---------------- CSR construction ------------------------------------------
__global__ void k_count_deg(const int* __restrict__ ei, int* deg) {
    int e = blockIdx.x * blockDim.x + threadIdx.x;
    if (e < NEDGE) atomicAdd(&deg[clampi(ei[NEDGE + e], 0, NNODE - 1)], 1);
}
__global__ void k_scan1(const int* __restrict__ deg, int* rowptr, int* bsum) {
    int b = blockIdx.x, tid = threadIdx.x;
    int i = b * 1024 + tid;
    int v = (i < NNODE) ? (deg[i] + 1) : 0;   // +1 self loop
    int lane = tid & 31, w = tid >> 5;
    int x = v;
#pragma unroll
    for (int off = 1; off < 32; off <<= 1) {
        int y = __shfl_up_sync(0xffffffffu, x, off);
        if (lane >= off) x += y;
    }
    __shared__ int ws[32];
    if (lane == 31) ws[w] = x;
    __syncthreads();
    if (w == 0) {
        int s = ws[lane];
#pragma unroll
        for (int off = 1; off < 32; off <<= 1) {
            int y = __shfl_up_sync(0xffffffffu, s, off);
            if (lane >= off) s += y;
        }
        ws[lane] = s;
    }
    __syncthreads();
    int wo = (w > 0) ? ws[w - 1] : 0;
    int incl = x + wo;
    if (i < NNODE) rowptr[i] = incl - v;
    if (tid == 1023) bsum[b] = incl;
}
__global__ void k_scan2(const int* __restrict__ bsum, int* boff, int* rowptr) {
    if (threadIdx.x == 0) {
        int s = 0;
        for (int b = 0; b < NBLK; b++) { boff[b] = s; s += bsum[b]; }
        rowptr[NNODE] = s;
    }
}
__global__ void k_scan3(int* rowptr, int* cursor, const int* __restrict__ boff) {
    int i = blockIdx.x * blockDim.x + threadIdx.x;
    if (i < NNODE) {
        int r = rowptr[i] + boff[i >> 10];
        rowptr[i] = r;
        cursor[i] = r;
    }
}
__global__ void k_scatter(const int* __restrict__ ei, int* cursor, int* srcs) {
    int e = blockIdx.x * blockDim.x + threadIdx.x;
    if (e < NEDGE) {
        int s = clampi(ei[e], 0, NNODE - 1);
        int d = clampi(ei[NEDGE + e], 0, NNODE - 1);
        int pos = atomicAdd(&cursor[d], 1);
        if (pos >= 0 && pos < EPAD) srcs[pos] = s;
    } else if (e < EPAD) {
        int i = e - NEDGE;
        int pos = atomicAdd(&cursor[i], 1);
        if (pos >= 0 && pos < EPAD) srcs[pos] = i;
    }
}

// ---------------- weight split/transpose: W[K][N] -> hi/lo bf16 [N][K] ------
__global__ void k_split_w(const float* __restrict__ W, uint16_t* __restrict__ WH,
                          uint16_t* __restrict__ WL, int K, int N) {
    int i = blockIdx.x * blockDim.x + threadIdx.x;
    if (i < K * N) {
        int k = i / N, n = i % N;
        float v = W[i];
        uint32_t hw = pack_bf16x2(v, 0.f);
        float hf = __uint_as_float(hw << 16);
        uint32_t lw = pack_bf16x2(v - hf, 0.f);
        WH[n * K + k] = (uint16_t)(hw & 0xffffu);
        WL[n * K + k] = (uint16_t)(lw & 0xffffu);
    }
}

// ---------------- bf16-split tensor-core GEMM + fused logits ----------------
// Double-buffered smem (1 sync per K-tile). PRESPLIT path: pure cp.async.
// GEMM1 path: A fp32 staged via regs (split in flight), B via cp.async.
template<int BN, int NOUT, bool PRESPLIT, bool HALF_C>
__global__ void __launch_bounds__(256, 2)
k_gemm_mma(const float* __restrict__ A,
           const uint16_t* __restrict__ AH, const uint16_t* __restrict__ AL,
           const uint16_t* __restrict__ BH, const uint16_t* __restrict__ BL,
           const float* __restrict__ bias, void* __restrict__ C, int M,
           const float* __restrict__ a_src, const float* __restrict__ a_dst,
           float* __restrict__ als_out, float* __restrict__ ald_out) {
    constexpr int RS = 40;                 // smem row stride (halves)
    constexpr int WN = BN / 2;
    constexpr int NT = WN / 8;
    constexpr int NP = NT / 2;
    constexpr int ABYTES = 128 * RS * 2;   // 10240
    constexpr int BBYTES = BN * RS * 2;
    constexpr int AOFF_H = 0, AOFF_L = ABYTES;
    constexpr int BOFF_H = 2 * ABYTES, BOFF_L = 2 * ABYTES + BBYTES;
    constexpr int STAGE = 2 * ABYTES + 2 * BBYTES;
    constexpr int B_CH = BN / 64;          // 16B chunks per thread per B array

    extern __shared__ __align__(16) char smem[];
    const uint32_t sb = (uint32_t)__cvta_generic_to_shared(smem);

    const int tid  = threadIdx.x;
    const int wid  = tid >> 5, lane = tid & 31;
    const int wm   = wid & 3, wn = wid >> 2;
    const int g    = lane >> 2, tq = lane & 3;
    const int brow = blockIdx.x * 128;
    const int bcol = blockIdx.y * BN;

    float acc[2][NT][4];
#pragma unroll
    for (int mt = 0; mt < 2; mt++)
#pragma unroll
        for (int nt = 0; nt < NT; nt++)
#pragma unroll
            for (int r = 0; r < 4; r++) acc[mt][nt][r] = 0.f;

    // per-lane ldmatrix byte offsets (within each array)
    const int lane8 = lane & 7, lh = (lane >> 3) & 1, lq = lane >> 4;
    uint32_t aOff[2], bOff[NP];
#pragma unroll
    for (int mt = 0; mt < 2; mt++) {
        int ar = wm * 32 + mt * 16 + lane8 + lh * 8;
        aOff[mt] = (uint32_t)(ar * RS + lq * 8) * 2;
    }
#pragma unroll
    for (int p = 0; p < NP; p++) {
        int br = wn * WN + p * 16 + lane8 + lq * 8;
        bOff[p] = (uint32_t)(br * RS + lh * 8) * 2;
    }

    // cp.async issue of B (always) into given stage
    auto cpB = [&](int k0, int stage) {
        uint32_t sbase = sb + stage * STAGE;
#pragma unroll
        for (int u = 0; u < B_CH; u++) {
            int q = tid + u * 256;
            int row = q >> 2, c8 = q & 3;
            size_t gi = (size_t)(bcol + row) * 256 + k0 + c8 * 8;
            uint32_t d = sbase + (uint32_t)(row * (RS * 2) + c8 * 16);
            CP_A16(d + BOFF_H, BH + gi, 16);
            CP_A16(d + BOFF_L, BL + gi, 16);
        }
    };
    // cp.async issue of A (PRESPLIT only)
    auto cpA = [&](int k0, int stage) {
        uint32_t sbase = sb + stage * STAGE;
#pragma unroll
        for (int u = 0; u < 2; u++) {
            int q = tid + u * 256;
            int row = q >> 2, c8 = q & 3;
            int gr = brow + row;
            int sz = (gr < M) ? 16 : 0;
            int grc = (gr < M) ? gr : 0;
            size_t gi = (size_t)grc * 256 + k0 + c8 * 8;
            uint32_t d = sbase + (uint32_t)(row * (RS * 2) + c8 * 16);
            CP_A16(d + AOFF_H, AH + gi, sz);
            CP_A16(d + AOFF_L, AL + gi, sz);
        }
    };

    // register staging for fp32 A (GEMM1 path)
    float4 aS[4];
    auto loadA = [&](int k0) {
#pragma unroll
        for (int u = 0; u < 4; u++) {
            int q = tid + u * 256;
            int row = q >> 3, f4 = q & 7;
            int gr = brow + row;
            aS[u] = make_float4(0.f, 0.f, 0.f, 0.f);
            if (gr < M) aS[u] = *reinterpret_cast<const float4*>(&A[(size_t)gr * 256 + k0 + f4 * 4]);
        }
    };
    auto storeA = [&](int stage) {
        uint16_t* pAh = reinterpret_cast<uint16_t*>(smem + stage * STAGE + AOFF_H);
        uint16_t* pAl = reinterpret_cast<uint16_t*>(smem + stage * STAGE + AOFF_L);
#pragma unroll
        for (int u = 0; u < 4; u++) {
            int q = tid + u * 256;
            int row = q >> 3, f4 = q & 7;
            int idx = row * RS + f4 * 4;
            float v[4] = {aS[u].x, aS[u].y, aS[u].z, aS[u].w};
#pragma unroll
            for (int h2i = 0; h2i < 2; h2i++) {
                uint32_t hw = pack_bf16x2(v[h2i * 2], v[h2i * 2 + 1]);
                float f0 = __uint_as_float(hw << 16);
                float f1 = __uint_as_float(hw & 0xffff0000u);
                uint32_t lw = pack_bf16x2(v[h2i * 2] - f0, v[h2i * 2 + 1] - f1);
                *reinterpret_cast<uint32_t*>(pAh + idx + h2i * 2) = hw;
                *reinterpret_cast<uint32_t*>(pAl + idx + h2i * 2) = lw;
            }
        }
    };

    auto compute = [&](int stage) {
        uint32_t sbase = sb + stage * STAGE;
#pragma unroll
        for (int ks = 0; ks < 2; ks++) {
            const uint32_t kb = ks * 32;
            uint32_t ah[2][4], al[2][4];
            LDSM_X4(ah[0], sbase + AOFF_H + aOff[0] + kb);
            LDSM_X4(ah[1], sbase + AOFF_H + aOff[1] + kb);
            LDSM_X4(al[0], sbase + AOFF_L + aOff[0] + kb);
            LDSM_X4(al[1], sbase + AOFF_L + aOff[1] + kb);
#pragma unroll
            for (int p = 0; p < NP; p++) {
                uint32_t bh[4], bl[4];
                LDSM_X4(bh, sbase + BOFF_H + bOff[p] + kb);
                LDSM_X4(bl, sbase + BOFF_L + bOff[p] + kb);
#pragma unroll
                for (int mt = 0; mt < 2; mt++) {
                    mma_bf16(acc[mt][2 * p],     ah[mt], bh);
                    mma_bf16(acc[mt][2 * p],     ah[mt], bl);
                    mma_bf16(acc[mt][2 * p],     al[mt], bh);
                    mma_bf16(acc[mt][2 * p + 1], ah[mt], bh + 2);
                    mma_bf16(acc[mt][2 * p + 1], ah[mt], bl + 2);
                    mma_bf16(acc[mt][2 * p + 1], al[mt], bh + 2);
                }
            }
        }
    };

    // ---- pipelined mainloop (8 K-tiles of 32), 2 smem stages, 1 sync/tile --
    if (PRESPLIT) {
        cpA(0, 0); cpB(0, 0); CP_COMMIT();
        CP_WAIT0(); __syncthreads();
        int buf = 0;
        for (int t = 0; t < 8; t++) {
            if (t < 7) { cpA((t + 1) * 32, buf ^ 1); cpB((t + 1) * 32, buf ^ 1); CP_COMMIT(); }
            compute(buf);
            if (t < 7) { CP_WAIT0(); __syncthreads(); buf ^= 1; }
        }
    } else {
        cpB(0, 0); CP_COMMIT();
        loadA(0); storeA(0);
        CP_WAIT0(); __syncthreads();
        int buf = 0;
        for (int t = 0; t < 8; t++) {
            if (t < 7) { cpB((t + 1) * 32, buf ^ 1); CP_COMMIT(); loadA((t + 1) * 32); }
            compute(buf);
            if (t < 7) { storeA(buf ^ 1); CP_WAIT0(); __syncthreads(); buf ^= 1; }
        }
    }

    // epilogue
#pragma unroll
    for (int mt = 0; mt < 2; mt++) {
        int r0 = brow + wm * 32 + mt * 16 + g;
        int r1 = r0 + 8;
#pragma unroll
        for (int nt = 0; nt < NT; nt++) {
            int col = bcol + wn * WN + nt * 8 + tq * 2;
            if (HALF_C) {
                __half2* Ch = reinterpret_cast<__half2*>(C);
                if (r0 < M)
                    Ch[(size_t)r0 * (NOUT / 2) + col / 2] =
                        __floats2half2_rn(acc[mt][nt][0], acc[mt][nt][1]);
                if (r1 < M)
                    Ch[(size_t)r1 * (NOUT / 2) + col / 2] =
                        __floats2half2_rn(acc[mt][nt][2], acc[mt][nt][3]);
            } else {
                float* Cf = reinterpret_cast<float*>(C);
                float b0 = 0.f, b1 = 0.f;
                if (bias) { b0 = bias[col]; b1 = bias[col + 1]; }
                if (r0 < M)
                    *reinterpret_cast<float2*>(&Cf[(size_t)r0 * NOUT + col]) =
                        make_float2(acc[mt][nt][0] + b0, acc[mt][nt][1] + b1);
                if (r1 < M)
                    *reinterpret_cast<float2*>(&Cf[(size_t)r1 * NOUT + col]) =
                        make_float2(acc[mt][nt][2] + b0, acc[mt][nt][3] + b1);
            }
        }
    }

    // fused attention logits (BN==128): head = blockIdx.y*2 + wn (fp32 acc)
    if (als_out) {
        int head = blockIdx.y * 2 + wn;
#pragma unroll
        for (int mt = 0; mt < 2; mt++) {
#pragma unroll
            for (int half = 0; half < 2; half++) {
                float ps = 0.f, pd = 0.f;
#pragma unroll
                for (int nt = 0; nt < NT; nt++) {
                    int col = bcol + wn * WN + nt * 8 + tq * 2;
                    float a0 = acc[mt][nt][half * 2 + 0];
                    float a1 = acc[mt][nt][half * 2 + 1];
                    ps += a0 * a_src[col] + a1 * a_src[col + 1];
                    pd += a0 * a_dst[col] + a1 * a_dst[col + 1];
                }
                ps += __shfl_xor_sync(0xffffffffu, ps, 1);
                pd += __shfl_xor_sync(0xffffffffu, pd, 1);
                ps += __shfl_xor_sync(0xffffffffu, ps, 2);
                pd += __shfl_xor_sync(0xffffffffu, pd, 2);
                int row = brow + wm * 32 + mt * 16 + g + half * 8;
                if (tq == 0 && row < M) {
                    als_out[row * NHEAD + head] = ps;
                    ald_out[row * NHEAD + head] = pd;
                }
            }
        }
    }
}

// ---------------- warp-synchronous aggregation (fp16 messages) --------------
// One node per 128-thread block; warp w owns head w (32 half2 channels).
__global__ void __launch_bounds__(128)
k_gat_aggregate(const __half2* __restrict__ hsrc,
                const int* __restrict__ rowptr,
                const int* __restrict__ srcs,
                const float* __restrict__ als,
                const float* __restrict__ ald,
                const float* __restrict__ bias,
                uint16_t* __restrict__ outh, uint16_t* __restrict__ outl) {
    int n = blockIdx.x;
    int w = threadIdx.x >> 5;    // head == warp
    int lane = threadIdx.x & 31;
    int c2 = w * 32 + lane;

    int p0  = rowptr[n];
    int deg = rowptr[n + 1] - p0;

    float aldv = __ldg(&ald[n * NHEAD + w]);
    float accx = 0.f, accy = 0.f, dsum = 0.f;

    for (int base = 0; base < deg; base += 32) {
        int j = base + lane;
        int s = 0;
        float wt = 0.f;
        if (j < deg) {
            s = srcs[p0 + j];
            float e = als[s * NHEAD + w] + aldv;
            e = (e > 0.f) ? e : 0.2f * e;
            wt = __expf(e);
            dsum += wt;
        }
        int lim = min(32, deg - base);
#pragma unroll 4
        for (int j2 = 0; j2 < lim; j2++) {
            int   ss = __shfl_sync(0xffffffffu, s,  j2);
            float ww = __shfl_sync(0xffffffffu, wt, j2);
            float2 v = __half22float2(hsrc[(size_t)ss * 128 + c2]);
            accx += ww * v.x;
            accy += ww * v.y;
        }
    }

#pragma unroll
    for (int off = 16; off >= 1; off >>= 1)
        dsum += __shfl_xor_sync(0xffffffffu, dsum, off);

    float inv = 1.f / dsum;
    float o0 = accx * inv + bias[2 * c2];
    float o1 = accy * inv + bias[2 * c2 + 1];
    o0 = (o0 > 0.f) ? o0 : expm1f(o0);
    o1 = (o1 > 0.f) ? o1 : expm1f(o1);

    uint32_t hw = pack_bf16x2(o0, o1);
    float f0 = __uint_as_float(hw << 16);
    float f1 = __uint_as_float(hw & 0xffff0000u);
    uint32_t lw = pack_bf16x2(o0 - f0, o1 - f1);
    reinterpret_cast<uint32_t*>(outh)[(size_t)n * 128 + c2] = hw;
    reinterpret_cast<uint32_t*>(outl)[(size_t)n * 128 + c2] = lw;
}

// ---------------- launch ----------------------------------------------------
extern "C" void kernel_launch(void* const* d_in, const int* in_sizes, int n_in,
                              void* d_out, int out_size) {
    const float* x     = (const float*)d_in[0];
    const int*   ei    = (const int*)d_in[1];   // int32 (JAX x64 disabled)
    const float* W1    = (const float*)d_in[3];
    const float* asrc1 = (const float*)d_in[4];
    const float* adst1 = (const float*)d_in[5];
    const float* b1    = (const float*)d_in[6];
    const float* W2    = (const float*)d_in[7];
    const float* asrc2 = (const float*)d_in[8];
    const float* adst2 = (const float*)d_in[9];
    const float* b2    = (const float*)d_in[10];
    const float* fcW   = (const float*)d_in[11];
    const float* fcb   = (const float*)d_in[12];
    float* out = (float*)d_out;

    __half* t;
    float *als, *ald;
    uint16_t *h1h, *h1l, *h2h, *h2l;
    uint16_t *w1h, *w1l, *w2h, *w2l, *wfh, *wfl;
    int *deg, *rowptr, *cursor, *srcs, *bsum, *boff;
    cudaGetSymbolAddress((void**)&t, g_t);
    cudaGetSymbolAddress((void**)&h1h, g_h1h);
    cudaGetSymbolAddress((void**)&h1l, g_h1l);
    cudaGetSymbolAddress((void**)&h2h, g_h2h);
    cudaGetSymbolAddress((void**)&h2l, g_h2l);
    cudaGetSymbolAddress((void**)&als, g_als);
    cudaGetSymbolAddress((void**)&ald, g_ald);
    cudaGetSymbolAddress((void**)&w1h, g_w1h);
    cudaGetSymbolAddress((void**)&w1l, g_w1l);
    cudaGetSymbolAddress((void**)&w2h, g_w2h);
    cudaGetSymbolAddress((void**)&w2l, g_w2l);
    cudaGetSymbolAddress((void**)&wfh, g_wfh);
    cudaGetSymbolAddress((void**)&wfl, g_wfl);
    cudaGetSymbolAddress((void**)&deg, g_deg);
    cudaGetSymbolAddress((void**)&rowptr, g_rowptr);
    cudaGetSymbolAddress((void**)&cursor, g_cursor);
    cudaGetSymbolAddress((void**)&srcs, g_srcs);
    cudaGetSymbolAddress((void**)&bsum, g_bsum);
    cudaGetSymbolAddress((void**)&boff, g_boff);

    constexpr int SMEM_BIG = 2 * (2 * 10240 + 2 * 10240);   // 81920
    constexpr int SMEM_FC  = 2 * (2 * 10240 + 2 * 5120);    // 61440

    // one-time init (first call = correctness run, outside graph capture)
    static cudaStream_t s2 = nullptr;
    static cudaEvent_t evFork = nullptr, evJoin = nullptr;
    if (s2 == nullptr) {
        cudaStreamCreateWithFlags(&s2, cudaStreamNonBlocking);
        cudaEventCreateWithFlags(&evFork, cudaEventDisableTiming);
        cudaEventCreateWithFlags(&evJoin, cudaEventDisableTiming);
        cudaFuncSetAttribute((const void*)k_gemm_mma<128, 256, false, true>,
                             cudaFuncAttributeMaxDynamicSharedMemorySize, SMEM_BIG);
        cudaFuncSetAttribute((const void*)k_gemm_mma<128, 256, true, true>,
                             cudaFuncAttributeMaxDynamicSharedMemorySize, SMEM_BIG);
        cudaFuncSetAttribute((const void*)k_gemm_mma<64, 64, true, false>,
                             cudaFuncAttributeMaxDynamicSharedMemorySize, SMEM_FC);
    }

    const int NTILE = (NNODE + 127) / 128;   // 391
    dim3 gbig(NTILE, 2);
    dim3 gfc(NTILE, 1);

    // fork side stream
    cudaEventRecord(evFork, 0);
    cudaStreamWaitEvent(s2, evFork, 0);

    // main #1 (overall #3 after 2 harness kernels)
    k_split_w<<<(FDIM * FDIM + 255) / 256, 256>>>(W1, w1h, w1l, FDIM, FDIM);
    cudaMemsetAsync(deg, 0, NNODE * sizeof(int), s2);
    k_count_deg<<<(NEDGE + 255) / 256, 256, 0, s2>>>(ei, deg);
    k_scan1<<<NBLK, 1024, 0, s2>>>(deg, rowptr, bsum);

    // overall #6: layer-1 GEMM (profiled by ncu -s 5 -c 1)
    k_gemm_mma<128, 256, false, true><<<gbig, 256, SMEM_BIG>>>(
        x, nullptr, nullptr, w1h, w1l, nullptr, t, NNODE, asrc1, adst1, als, ald);

    // rest of CSR + weight splits on side stream
    k_scan2<<<1, 32, 0, s2>>>(bsum, boff, rowptr);
    k_scan3<<<NBLK, 1024, 0, s2>>>(rowptr, cursor, boff);
    k_scatter<<<(EPAD + 255) / 256, 256, 0, s2>>>(ei, cursor, srcs);
    k_split_w<<<(FDIM * FDIM + 255) / 256, 256, 0, s2>>>(W2, w2h, w2l, FDIM, FDIM);
    k_split_w<<<(FDIM * OUTD + 255) / 256, 256, 0, s2>>>(fcW, wfh, wfl, FDIM, OUTD);
    cudaEventRecord(evJoin, s2);

    // join: aggregation needs CSR; layer-2 GEMM needs W2 split
    cudaStreamWaitEvent(0, evJoin, 0);

    // layer 1 aggregate -> h1 (bf16 split); one node per block
    k_gat_aggregate<<<NNODE, 128>>>((const __half2*)t, rowptr, srcs, als, ald,
                                    b1, h1h, h1l);

    // layer 2
    k_gemm_mma<128, 256, true, true><<<gbig, 256, SMEM_BIG>>>(
        nullptr, h1h, h1l, w2h, w2l, nullptr, t, NNODE, asrc2, adst2, als, ald);
    k_gat_aggregate<<<NNODE, 128>>>((const __half2*)t, rowptr, srcs, als, ald,
                                    b2, h2h, h2l);

    // fc head (fp32 out + bias)
    k_gemm_mma<64, 64, true, false><<<gfc, 256, SMEM_FC>>>(
        nullptr, h2h, h2l, wfh, wfl, fcb, out, NNODE,
        nullptr, nullptr, nullptr, nullptr);
}